// round 15
// baseline (speedup 1.0000x reference)
#include <cuda_runtime.h>
#include <cstdint>
#include <cstddef>

// Problem constants (static in reference)
constexpr int Mm = 512, Nn = 4096, Kdim = 4096, Dd = 128, Hh = 32, Ll = 4096, Pp = 3584;
constexpr size_t OUT0 = (size_t)Mm * Nn;

// Scratch (device globals: allocation-free per harness rules)
__device__ float g_q [(size_t)Hh * Mm * Dd];   // 8 MB [H][M][D]
__device__ float g_Kn[(size_t)Hh * Mm * Dd];   // 8 MB new K rows [H][M][D]
__device__ float g_Vn[(size_t)Hh * Mm * Dd];   // 8 MB new V rows [H][M][D]
__device__ float g_S [(size_t)Hh * Mm * Ll];   // 256 MB raw scores [H*M][L]
__device__ float g_invs[Hh * Mm];              // 1/sum(exp(s)) per row

// ---------------------------------------------------------------------------
// PTX helpers (all baseline, no sm_103a-suffixed features)
// ---------------------------------------------------------------------------
__device__ __forceinline__ uint32_t smem_u32(const void* p) {
    uint32_t a;
    asm("{ .reg .u64 t; cvta.to.shared.u64 t, %1; cvt.u32.u64 %0, t; }" : "=r"(a) : "l"(p));
    return a;
}
// Cheap tf32 split: hi = truncate to 13 mantissa bits (valid tf32),
// lo = f - hi (exactly representable in tf32).
__device__ __forceinline__ void tf32split(uint32_t fraw, uint32_t& hi, uint32_t& lo) {
    hi = fraw & 0xFFFFE000u;
    lo = __float_as_uint(__uint_as_float(fraw) - __uint_as_float(hi));
}
__device__ __forceinline__ void mma8(float* c, const uint32_t* a, const uint32_t* b) {
    asm("mma.sync.aligned.m16n8k8.row.col.f32.tf32.tf32.f32 "
        "{%0,%1,%2,%3}, {%4,%5,%6,%7}, {%8,%9}, {%0,%1,%2,%3};"
        : "+f"(c[0]), "+f"(c[1]), "+f"(c[2]), "+f"(c[3])
        : "r"(a[0]), "r"(a[1]), "r"(a[2]), "r"(a[3]), "r"(b[0]), "r"(b[1]));
}
__device__ __forceinline__ void ldsm4(uint32_t& r0, uint32_t& r1, uint32_t& r2, uint32_t& r3,
                                      uint32_t addr) {
    asm volatile("ldmatrix.sync.aligned.m8n8.x4.shared.b16 {%0,%1,%2,%3}, [%4];"
                 : "=r"(r0), "=r"(r1), "=r"(r2), "=r"(r3) : "r"(addr));
}
__device__ __forceinline__ void cpasync16(uint32_t dst, const float* src) {
    asm volatile("cp.async.cg.shared.global [%0], [%1], 16;" :: "r"(dst), "l"(src));
}
#define CP_COMMIT() asm volatile("cp.async.commit_group;" ::: "memory")
#define CP_WAIT1()  asm volatile("cp.async.wait_group 1;" ::: "memory")

// ---------------------------------------------------------------------------
// SMEM: 3-stage ring, K=32 slab, CTA tile 128x64 (2 CTAs per SM).
//   A raw f32 [128][36] (4608 w)
//   B raw: n-major [32][76] (2432 w) or K-major [64][36] (2304 w)
// Stage = 7040 words = 28160 B; 3 stages = 84480 B per CTA (2 CTAs = 169 KB).
// A_STR=36: LDSM phase banks (4r+c)&31 distinct. B_STR=76: (12*t4+g)&31 distinct.
// ---------------------------------------------------------------------------
#define A_STR 36
#define B_STR 76
#define B_OFF_W 4608
#define STAGE_W 7040
constexpr int SMEMSZ = 3 * STAGE_W * 4;   // 84480 B

// B rows from two sources split at `split` (cache vs freshly-projected rows)
struct BSrc { const float* p0; const float* p1; int split; size_t ld; };
__device__ __forceinline__ const float* brow(const BSrc& s, int r) {
    return (r < s.split) ? s.p0 + (size_t)r * s.ld : s.p1 + (size_t)(r - s.split) * s.ld;
}

// ---- stage issue (256 threads) ----
// A tile 128x32: each thread 16 floats (4 cp.async)
__device__ __forceinline__ void issueA(uint32_t sb, const float* __restrict__ A,
                                       size_t lda, int am0, int kb, int tid) {
    int r = tid >> 1, kq = (tid & 1) * 16;
    const float* src = A + (size_t)(am0 + r) * lda + kb + kq;
    uint32_t dst = sb + (r * A_STR + kq) * 4;
    cpasync16(dst, src);       cpasync16(dst + 16, src + 4);
    cpasync16(dst + 32, src + 8); cpasync16(dst + 48, src + 12);
}
template <bool BKMAJOR>
__device__ __forceinline__ void issueB(uint32_t sb, const BSrc& bs, int bn0, int kb, int tid) {
    if (BKMAJOR) {  // [64 n][32 k], stride 36
        int n = tid >> 2, kq = (tid & 3) * 8;
        const float* src = brow(bs, bn0 + n) + kb + kq;
        uint32_t dst = sb + B_OFF_W * 4 + (n * A_STR + kq) * 4;
        cpasync16(dst, src); cpasync16(dst + 16, src + 4);
    } else {        // [32 k][64 n], stride 76
        int k = tid >> 3, n0 = (tid & 7) * 8;
        const float* src = brow(bs, kb + k) + bn0 + n0;
        uint32_t dst = sb + B_OFF_W * 4 + (k * B_STR + n0) * 4;
        cpasync16(dst, src); cpasync16(dst + 16, src + 4);
    }
}
// EXPA path: A staged via LDG -> exp -> STS (exp paid once per element)
struct F16 { float4 v[4]; };
__device__ __forceinline__ F16 ldgA(const float* __restrict__ A, size_t lda,
                                    int am0, int kb, int tid) {
    int r = tid >> 1, kq = (tid & 1) * 16;
    const float* p = A + (size_t)(am0 + r) * lda + kb + kq;
    F16 o;
#pragma unroll
    for (int i = 0; i < 4; i++) o.v[i] = *(const float4*)(p + i * 4);
    return o;
}
__device__ __forceinline__ void stsExpA(uint32_t sb, const F16& o, int tid) {
    int r = tid >> 1, kq = (tid & 1) * 16;
    uint32_t d0 = sb + (r * A_STR + kq) * 4;
#pragma unroll
    for (int i = 0; i < 4; i++) {
        float e0 = __expf(o.v[i].x), e1 = __expf(o.v[i].y);
        float e2 = __expf(o.v[i].z), e3 = __expf(o.v[i].w);
        asm volatile("st.shared.v4.f32 [%0], {%1,%2,%3,%4};"
                     :: "r"(d0 + i * 16), "f"(e0), "f"(e1), "f"(e2), "f"(e3) : "memory");
    }
}

// ---------------------------------------------------------------------------
// GEMM core: C[128,64] = A[128xK] * B[Kx64]
// 256 threads = 8 warps, 4M x 2N; warp tile 32x32 = 2x4 m16n8k8 tiles.
// Raw fp32 smem; LDSM fragments; mask-split in regs; 3xTF32 pass-major.
// K=32 per barrier (4 kt sub-steps), 3-stage cp.async ring.
// ---------------------------------------------------------------------------
template <int NCHUNK, bool BKMAJOR, bool EXPA>
__device__ __forceinline__ void gemm_tc(const float* __restrict__ A, size_t lda, int am0,
                                        BSrc bs, int bn0,
                                        uint32_t* sm, float (&acc)[2][4][4]) {
    const int tid = threadIdx.x;
    const int lane = tid & 31, wid = tid >> 5;
    const int wm0 = (wid >> 1) * 32, wn0 = (wid & 1) * 32;
    const int g = lane >> 2, t4 = lane & 3;
    const uint32_t sbase = smem_u32(sm);

#pragma unroll
    for (int i = 0; i < 2; i++)
#pragma unroll
        for (int j = 0; j < 4; j++)
#pragma unroll
            for (int q = 0; q < 4; q++) acc[i][j][q] = 0.f;

    F16 apre;
    // prolog: stages 0 and 1
    if (EXPA) {
        F16 a0 = ldgA(A, lda, am0, 0, tid);
        stsExpA(sbase, a0, tid);
        apre = ldgA(A, lda, am0, 32, tid);
    } else {
        issueA(sbase, A, lda, am0, 0, tid);
    }
    issueB<BKMAJOR>(sbase, bs, bn0, 0, tid);
    CP_COMMIT();
    if (!EXPA) issueA(sbase + STAGE_W * 4, A, lda, am0, 32, tid);
    issueB<BKMAJOR>(sbase + STAGE_W * 4, bs, bn0, 32, tid);
    CP_COMMIT();

    // per-thread constant fragment address components
    const uint32_t a_rowbase = (wm0 + (lane & 15)) * A_STR + ((lane >> 4) << 2);
    const uint32_t b_rowbase = (wn0 + (lane & 7) + ((lane & 16) ? 8 : 0)) * A_STR +
                               ((lane & 8) ? 4 : 0);

    int stg = 0;  // stage index of chunk c (mod 3)
#pragma unroll 1
    for (int c = 0; c < NCHUNK; c++) {
        CP_WAIT1();
        int stg1 = (stg == 2) ? 0 : stg + 1;     // stage of chunk c+1
        int stg2 = (stg1 == 2) ? 0 : stg1 + 1;   // stage of chunk c+2 (= c-1's, free)
        if (EXPA && c + 1 < NCHUNK)
            stsExpA(sbase + stg1 * STAGE_W * 4, apre, tid);
        __syncthreads();
        if (c + 2 < NCHUNK) {
            uint32_t nb = sbase + stg2 * STAGE_W * 4;
            if (!EXPA) issueA(nb, A, lda, am0, (c + 2) * 32, tid);
            issueB<BKMAJOR>(nb, bs, bn0, (c + 2) * 32, tid);
            if (EXPA) apre = ldgA(A, lda, am0, (c + 2) * 32, tid);
        }
        CP_COMMIT();

        const uint32_t aB = sbase + stg * STAGE_W * 4;
        const uint32_t bB = aB + B_OFF_W * 4;
        const uint32_t* Bs = (const uint32_t*)sm + stg * STAGE_W + B_OFF_W;

#pragma unroll
        for (int kt = 0; kt < 4; kt++) {
            // ---- A fragments (LDSM raw) + mask split ----
            uint32_t araw[2][4], ah[2][4], al[2][4];
#pragma unroll
            for (int i = 0; i < 2; i++)
                ldsm4(araw[i][0], araw[i][1], araw[i][2], araw[i][3],
                      aB + (a_rowbase + i * 16 * A_STR + kt * 8) * 4);
#pragma unroll
            for (int i = 0; i < 2; i++)
#pragma unroll
                for (int q = 0; q < 4; q++) tf32split(araw[i][q], ah[i][q], al[i][q]);
            // ---- B fragments + mask split ----
            uint32_t bh[4][2], bl[4][2];
            if (BKMAJOR) {
                uint32_t braw[4][2];
#pragma unroll
                for (int jp = 0; jp < 2; jp++) {
                    uint32_t r0, r1, r2, r3;
                    ldsm4(r0, r1, r2, r3, bB + (b_rowbase + jp * 16 * A_STR + kt * 8) * 4);
                    braw[jp * 2][0] = r0;     braw[jp * 2][1] = r1;
                    braw[jp * 2 + 1][0] = r2; braw[jp * 2 + 1][1] = r3;
                }
#pragma unroll
                for (int j = 0; j < 4; j++)
#pragma unroll
                    for (int q = 0; q < 2; q++) tf32split(braw[j][q], bh[j][q], bl[j][q]);
            } else {
                const int kc = kt * 8 + t4;
#pragma unroll
                for (int j = 0; j < 4; j++) {
                    tf32split(Bs[kc * B_STR + wn0 + j * 8 + g], bh[j][0], bl[j][0]);
                    tf32split(Bs[(kc + 4) * B_STR + wn0 + j * 8 + g], bh[j][1], bl[j][1]);
                }
            }
            // ---- MMAs, pass-major (8 independent accumulators per pass) ----
#pragma unroll
            for (int i = 0; i < 2; i++)
#pragma unroll
                for (int j = 0; j < 4; j++) mma8(acc[i][j], ah[i], bh[j]);
#pragma unroll
            for (int i = 0; i < 2; i++)
#pragma unroll
                for (int j = 0; j < 4; j++) mma8(acc[i][j], ah[i], bl[j]);
#pragma unroll
            for (int i = 0; i < 2; i++)
#pragma unroll
                for (int j = 0; j < 4; j++) mma8(acc[i][j], al[i], bh[j]);
        }
        __syncthreads();
        stg = stg1;
    }
}

__device__ __forceinline__ void store_acc(float (&acc)[2][4][4], float* __restrict__ dst,
                                          size_t ldd, const float* __restrict__ rowscale) {
    const int tid = threadIdx.x;
    const int lane = tid & 31, wid = tid >> 5;
    const int wm0 = (wid >> 1) * 32, wn0 = (wid & 1) * 32;
    const int g = lane >> 2, t4 = lane & 3;
#pragma unroll
    for (int i = 0; i < 2; i++) {
        int r0 = wm0 + i * 16 + g;
        float s0 = rowscale ? rowscale[r0] : 1.f;
        float s1 = rowscale ? rowscale[r0 + 8] : 1.f;
#pragma unroll
        for (int j = 0; j < 4; j++) {
            int cn = wn0 + j * 8 + t4 * 2;
            *(float2*)&dst[(size_t)r0 * ldd + cn] =
                make_float2(acc[i][j][0] * s0, acc[i][j][1] * s0);
            *(float2*)&dst[(size_t)(r0 + 8) * ldd + cn] =
                make_float2(acc[i][j][2] * s1, acc[i][j][3] * s1);
        }
    }
}

// ---------------------------------------------------------------------------
// Kernels (all 256 threads, 2 CTAs per SM)
// ---------------------------------------------------------------------------
extern __shared__ uint32_t dsm_u32[];

// QKV: C = X @ W_z; W is [k][n] -> B n-major. 64-wide n-tiles.
// blockIdx.x: z*64 + head*2 + nh  (192 total); blockIdx.y: m-block (4)
__global__ __launch_bounds__(256, 2)
void k_qkv(const float* __restrict__ X, const float* __restrict__ Wq,
           const float* __restrict__ Wk, const float* __restrict__ Wv) {
    int z = blockIdx.x >> 6, r6 = blockIdx.x & 63;
    int head = r6 >> 1, nh = r6 & 1;
    int bm0 = blockIdx.y * 128;
    const float* W = (z == 0) ? Wq : (z == 1) ? Wk : Wv;
    BSrc bs{W, W, Kdim, (size_t)Nn};
    float acc[2][4][4];
    gemm_tc<Kdim / 32, false, false>(X, Kdim, bm0, bs, head * 128 + nh * 64, dsm_u32, acc);
    float* dst = (z == 0) ? g_q  + ((size_t)head * Mm + bm0) * Dd
               : (z == 1) ? g_Kn + ((size_t)head * Mm + bm0) * Dd
                          : g_Vn + ((size_t)head * Mm + bm0) * Dd;
    store_acc(acc, dst + nh * 64, Dd, nullptr);
}

// Scores: S = q @ K^T; K-cache [l][d] K-major -> LDSM both operands
__global__ __launch_bounds__(256, 2)
void k_scores(const float* __restrict__ cacheK) {
    int h = blockIdx.z, bm0 = blockIdx.y * 128, l0 = blockIdx.x * 64;
    BSrc bs{cacheK + (size_t)h * Ll * Dd, g_Kn + (size_t)h * Mm * Dd, Pp, (size_t)Dd};
    float acc[2][4][4];
    gemm_tc<Dd / 32, true, false>(g_q + (size_t)h * Mm * Dd, Dd, bm0, bs, l0, dsm_u32, acc);
    store_acc(acc, g_S + ((size_t)h * Mm + bm0) * Ll + l0, Ll, nullptr);
}

// Output: out = (exp(S) @ V) * inv_sum; exp applied once per element at stage
// blockIdx.x: m-block*2 + nh (8); blockIdx.y: head (32)
__global__ __launch_bounds__(256, 2)
void k_out(const float* __restrict__ cacheV, float* __restrict__ dout) {
    int h = blockIdx.y, bm0 = (blockIdx.x >> 1) * 128, nh = blockIdx.x & 1;
    BSrc bs{cacheV + (size_t)h * Ll * Dd, g_Vn + (size_t)h * Mm * Dd, Pp, (size_t)Dd};
    float acc[2][4][4];
    gemm_tc<Ll / 32, false, true>(g_S + (size_t)h * Mm * Ll, Ll, bm0, bs, nh * 64,
                                  dsm_u32, acc);
    store_acc(acc, dout + (size_t)bm0 * Nn + h * Dd + nh * 64, Nn, g_invs + h * Mm + bm0);
}

// Dual-exp row kernel: reads raw S, writes normalized perturb + invs.
__global__ __launch_bounds__(256)
void softmax_rows(const float* __restrict__ noise, float* __restrict__ dout) {
    const int row = blockIdx.x;  // h*Mm + m
    const float* S = g_S + (size_t)row * Ll;
    const float* nz = noise + (size_t)row * Ll;
    float* pout = dout + OUT0 + (size_t)row * Ll;
    __shared__ float ep[Ll];
    __shared__ float r1[256], r2[256];
    const int tid = threadIdx.x;

    float ss = 0.f, sp = 0.f;
    for (int l = tid; l < Ll; l += 256) {
        float s = S[l];
        ss += __expf(s);
        float e2 = __expf((s + nz[l]) * (1.0f / 1.5f));
        ep[l] = e2;
        sp += e2;
    }
    r1[tid] = ss; r2[tid] = sp;
    __syncthreads();
    for (int st = 128; st > 0; st >>= 1) {
        if (tid < st) { r1[tid] += r1[tid + st]; r2[tid] += r2[tid + st]; }
        __syncthreads();
    }
    if (tid == 0) g_invs[row] = 1.0f / r1[0];
    const float ip = 1.0f / r2[0];
    for (int l = tid; l < Ll; l += 256) pout[l] = ep[l] * ip;
}

// ---------------------------------------------------------------------------
// Launch
// ---------------------------------------------------------------------------
extern "C" void kernel_launch(void* const* d_in, const int* in_sizes, int n_in,
                              void* d_out, int out_size) {
    const float* X      = (const float*)d_in[0];
    const float* Wq     = (const float*)d_in[1];
    const float* Wk     = (const float*)d_in[2];
    const float* Wv     = (const float*)d_in[3];
    const float* noise  = (const float*)d_in[4];
    const float* cacheK = (const float*)d_in[5];
    const float* cacheV = (const float*)d_in[6];
    float* out = (float*)d_out;
    (void)in_sizes; (void)n_in; (void)out_size;   // P is static (3584)

    cudaFuncSetAttribute(k_qkv,    cudaFuncAttributeMaxDynamicSharedMemorySize, SMEMSZ);
    cudaFuncSetAttribute(k_scores, cudaFuncAttributeMaxDynamicSharedMemorySize, SMEMSZ);
    cudaFuncSetAttribute(k_out,    cudaFuncAttributeMaxDynamicSharedMemorySize, SMEMSZ);

    k_qkv<<<dim3(192, 4), 256, SMEMSZ>>>(X, Wq, Wk, Wv);
    k_scores<<<dim3(64, 4, 32), 256, SMEMSZ>>>(cacheK);
    softmax_rows<<<Hh * Mm, 256>>>(noise, out);
    k_out<<<dim3(8, 32), 256, SMEMSZ>>>(cacheV, out);
}

// round 16
// speedup vs baseline: 1.1586x; 1.1586x over previous
#include <cuda_runtime.h>
#include <cstdint>
#include <cstddef>

// Problem constants (static in reference)
constexpr int Mm = 512, Nn = 4096, Kdim = 4096, Dd = 128, Hh = 32, Ll = 4096, Pp = 3584;
constexpr size_t OUT0 = (size_t)Mm * Nn;

// Scratch (device globals: allocation-free per harness rules)
__device__ float g_q [(size_t)Hh * Mm * Dd];   // 8 MB [H][M][D]
__device__ float g_Kn[(size_t)Hh * Mm * Dd];   // 8 MB new K rows [H][M][D]
__device__ float g_Vn[(size_t)Hh * Mm * Dd];   // 8 MB new V rows [H][M][D]
__device__ float g_S [(size_t)Hh * Mm * Ll];   // 256 MB raw scores [H*M][L]
__device__ float g_invs[Hh * Mm];              // 1/sum(exp(s)) per row

// ---------------------------------------------------------------------------
// PTX helpers (all baseline, no sm_103a-suffixed features)
// ---------------------------------------------------------------------------
__device__ __forceinline__ uint32_t smem_u32(const void* p) {
    uint32_t a;
    asm("{ .reg .u64 t; cvta.to.shared.u64 t, %1; cvt.u32.u64 %0, t; }" : "=r"(a) : "l"(p));
    return a;
}
// tf32 mask split (for qkv)
__device__ __forceinline__ void tf32split(uint32_t fraw, uint32_t& hi, uint32_t& lo) {
    hi = fraw & 0xFFFFE000u;
    lo = __float_as_uint(__uint_as_float(fraw) - __uint_as_float(hi));
}
// bf16 pair split: (f0,f1) -> packed hi bf16x2 (f0 in low half) + packed lo bf16x2
__device__ __forceinline__ void bf16split2(float f0, float f1, uint32_t& h, uint32_t& l) {
    asm("cvt.rn.bf16x2.f32 %0, %1, %2;" : "=r"(h) : "f"(f1), "f"(f0));
    float h0 = __uint_as_float(h << 16);
    float h1 = __uint_as_float(h & 0xFFFF0000u);
    float r0 = f0 - h0, r1 = f1 - h1;
    asm("cvt.rn.bf16x2.f32 %0, %1, %2;" : "=r"(l) : "f"(r1), "f"(r0));
}
__device__ __forceinline__ void mma8(float* c, const uint32_t* a, const uint32_t* b) {
    asm("mma.sync.aligned.m16n8k8.row.col.f32.tf32.tf32.f32 "
        "{%0,%1,%2,%3}, {%4,%5,%6,%7}, {%8,%9}, {%0,%1,%2,%3};"
        : "+f"(c[0]), "+f"(c[1]), "+f"(c[2]), "+f"(c[3])
        : "r"(a[0]), "r"(a[1]), "r"(a[2]), "r"(a[3]), "r"(b[0]), "r"(b[1]));
}
__device__ __forceinline__ void mma16(float* c, const uint32_t* a, const uint32_t* b) {
    asm("mma.sync.aligned.m16n8k16.row.col.f32.bf16.bf16.f32 "
        "{%0,%1,%2,%3}, {%4,%5,%6,%7}, {%8,%9}, {%0,%1,%2,%3};"
        : "+f"(c[0]), "+f"(c[1]), "+f"(c[2]), "+f"(c[3])
        : "r"(a[0]), "r"(a[1]), "r"(a[2]), "r"(a[3]), "r"(b[0]), "r"(b[1]));
}
__device__ __forceinline__ void ldsm4(uint32_t& r0, uint32_t& r1, uint32_t& r2, uint32_t& r3,
                                      uint32_t addr) {
    asm volatile("ldmatrix.sync.aligned.m8n8.x4.shared.b16 {%0,%1,%2,%3}, [%4];"
                 : "=r"(r0), "=r"(r1), "=r"(r2), "=r"(r3) : "r"(addr));
}
__device__ __forceinline__ void ldsm4t(uint32_t& r0, uint32_t& r1, uint32_t& r2, uint32_t& r3,
                                       uint32_t addr) {
    asm volatile("ldmatrix.sync.aligned.m8n8.x4.trans.shared.b16 {%0,%1,%2,%3}, [%4];"
                 : "=r"(r0), "=r"(r1), "=r"(r2), "=r"(r3) : "r"(addr));
}
__device__ __forceinline__ void cpasync16(uint32_t dst, const float* src) {
    asm volatile("cp.async.cg.shared.global [%0], [%1], 16;" :: "r"(dst), "l"(src));
}
#define CP_COMMIT() asm volatile("cp.async.commit_group;" ::: "memory")
#define CP_WAIT2()  asm volatile("cp.async.wait_group 2;" ::: "memory")
#define STS128(a, x, y, z, w) \
    asm volatile("st.shared.v4.b32 [%0], {%1,%2,%3,%4};" \
                 :: "r"(a), "r"(x), "r"(y), "r"(z), "r"(w) : "memory")

// B rows from two sources split at `split` (cache vs freshly-projected rows)
struct BSrc { const float* p0; const float* p1; int split; size_t ld; };
__device__ __forceinline__ const float* brow(const BSrc& s, int r) {
    return (r < s.split) ? s.p0 + (size_t)r * s.ld : s.p1 + (size_t)(r - s.split) * s.ld;
}

// ===========================================================================
// Part 1: tf32 GEMM for QKV (identical to the proven R13 best path)
// ===========================================================================
#define A_STR 36
#define B_STR 140
#define B_OFF_W 4608
#define STAGE_W 9216
constexpr int SMEMSZ_TF = 4 * STAGE_W * 4;   // 147456 B

__device__ __forceinline__ void issueA(uint32_t sb, const float* __restrict__ A,
                                       size_t lda, int am0, int kb, int tid) {
    int r = tid >> 2, kq = (tid & 3) * 8;
    const float* src = A + (size_t)(am0 + r) * lda + kb + kq;
    uint32_t dst = sb + (r * A_STR + kq) * 4;
    cpasync16(dst, src);
    cpasync16(dst + 16, src + 4);
}
__device__ __forceinline__ void issueB(uint32_t sb, const BSrc& bs, int bn0, int kb, int tid) {
    int k = tid >> 4, n0 = (tid & 15) * 8;
    const float* src = brow(bs, kb + k) + bn0 + n0;
    uint32_t dst = sb + B_OFF_W * 4 + (k * B_STR + n0) * 4;
    cpasync16(dst, src);
    cpasync16(dst + 16, src + 4);
}

template <int NCHUNK>
__device__ __forceinline__ void gemm_tf32(const float* __restrict__ A, size_t lda, int am0,
                                          BSrc bs, int bn0,
                                          uint32_t* sm, float (&acc)[2][4][4]) {
    const int tid = threadIdx.x;
    const int lane = tid & 31, wid = tid >> 5;
    const int wm0 = (wid >> 2) * 32, wn0 = (wid & 3) * 32;
    const int g = lane >> 2, t4 = lane & 3;
    const uint32_t sbase = smem_u32(sm);

#pragma unroll
    for (int i = 0; i < 2; i++)
#pragma unroll
        for (int j = 0; j < 4; j++)
#pragma unroll
            for (int q = 0; q < 4; q++) acc[i][j][q] = 0.f;

    issueA(sbase, A, lda, am0, 0, tid);
    issueB(sbase, bs, bn0, 0, tid);
    CP_COMMIT();
    issueA(sbase + STAGE_W * 4, A, lda, am0, 32, tid);
    issueB(sbase + STAGE_W * 4, bs, bn0, 32, tid);
    CP_COMMIT();
    issueA(sbase + 2 * STAGE_W * 4, A, lda, am0, 64, tid);
    issueB(sbase + 2 * STAGE_W * 4, bs, bn0, 64, tid);
    CP_COMMIT();

    const uint32_t a_rowbase = (wm0 + (lane & 15)) * A_STR + ((lane >> 4) << 2);

#pragma unroll 1
    for (int c = 0; c < NCHUNK; c++) {
        CP_WAIT2();
        __syncthreads();
        if (c + 3 < NCHUNK) {
            uint32_t nb = sbase + ((c + 3) & 3) * STAGE_W * 4;
            issueA(nb, A, lda, am0, (c + 3) * 32, tid);
            issueB(nb, bs, bn0, (c + 3) * 32, tid);
        }
        CP_COMMIT();

        const uint32_t aB = sbase + (c & 3) * STAGE_W * 4;
        const uint32_t* Bs = (const uint32_t*)sm + (c & 3) * STAGE_W + B_OFF_W;

#pragma unroll
        for (int kt = 0; kt < 4; kt++) {
            uint32_t araw[2][4], ah[2][4], al[2][4];
#pragma unroll
            for (int i = 0; i < 2; i++)
                ldsm4(araw[i][0], araw[i][1], araw[i][2], araw[i][3],
                      aB + (a_rowbase + i * 16 * A_STR + kt * 8) * 4);
#pragma unroll
            for (int i = 0; i < 2; i++)
#pragma unroll
                for (int q = 0; q < 4; q++) tf32split(araw[i][q], ah[i][q], al[i][q]);
            uint32_t bh[4][2], bl[4][2];
            const int kc = kt * 8 + t4;
#pragma unroll
            for (int j = 0; j < 4; j++) {
                tf32split(Bs[kc * B_STR + wn0 + j * 8 + g], bh[j][0], bl[j][0]);
                tf32split(Bs[(kc + 4) * B_STR + wn0 + j * 8 + g], bh[j][1], bl[j][1]);
            }
#pragma unroll
            for (int i = 0; i < 2; i++)
#pragma unroll
                for (int j = 0; j < 4; j++) mma8(acc[i][j], ah[i], bh[j]);
#pragma unroll
            for (int i = 0; i < 2; i++)
#pragma unroll
                for (int j = 0; j < 4; j++) mma8(acc[i][j], ah[i], bl[j]);
#pragma unroll
            for (int i = 0; i < 2; i++)
#pragma unroll
                for (int j = 0; j < 4; j++) mma8(acc[i][j], al[i], bh[j]);
        }
        __syncthreads();
    }
}

// ===========================================================================
// Part 2: bf16x3 GEMM for scores & out (m16n8k16, hi/lo split at stage time)
// SMEM per buffer (bytes):
//   Ahi [128 rows x 80B] @0, Alo @10240          (K-major packed bf16 pairs)
//   scores B (K-major packed, 128 rows x 80B): Bhi @20480, Blo @30720
//   out   B (n-major bf16 [32 k x 272B]):       Bhi @20480, Blo @29184
// Buffer stride 40960 B, double-buffered (81920 total).
// ===========================================================================
constexpr int BUF_BF = 40960;
constexpr int SMEMSZ_BF = 2 * BUF_BF;

struct F8 { float v[8]; };
__device__ __forceinline__ F8 ldg8(const float* p) {
    F8 o;
    float4 a = *(const float4*)p, b = *(const float4*)(p + 4);
    o.v[0] = a.x; o.v[1] = a.y; o.v[2] = a.z; o.v[3] = a.w;
    o.v[4] = b.x; o.v[5] = b.y; o.v[6] = b.z; o.v[7] = b.w;
    return o;
}
// split 8 f32 -> 4 hi + 4 lo packed words and store both (16B apart regions)
__device__ __forceinline__ void sts_split8(uint32_t hiaddr, uint32_t loaddr, const F8& o) {
    uint32_t h[4], l[4];
#pragma unroll
    for (int i = 0; i < 4; i++) bf16split2(o.v[2 * i], o.v[2 * i + 1], h[i], l[i]);
    STS128(hiaddr, h[0], h[1], h[2], h[3]);
    STS128(loaddr, l[0], l[1], l[2], l[3]);
}

// A / scores-B stage mapping: row = tid>>2 (128 rows), kq = (tid&3)*8
// K-major packed row: 80 bytes (16 words data + 4 pad); LDSM quads conflict-free.
template <bool EXPA>
__device__ __forceinline__ F8 ldgA_bf(const float* __restrict__ A, size_t lda,
                                      int am0, int kb, int tid) {
    int r = tid >> 2, kq = (tid & 3) * 8;
    F8 o = ldg8(A + (size_t)(am0 + r) * lda + kb + kq);
    if (EXPA) {
#pragma unroll
        for (int i = 0; i < 8; i++) o.v[i] = __expf(o.v[i]);
    }
    return o;
}
__device__ __forceinline__ void stsA_bf(uint32_t bb, const F8& o, int tid) {
    int r = tid >> 2, kq = (tid & 3) * 8;
    uint32_t a = bb + r * 80 + kq * 2;
    sts_split8(a, a + 10240, o);
}
// scores B (K-major rows = l)
__device__ __forceinline__ F8 ldgBk_bf(const BSrc& bs, int bn0, int kb, int tid) {
    int r = tid >> 2, kq = (tid & 3) * 8;
    return ldg8(brow(bs, bn0 + r) + kb + kq);
}
__device__ __forceinline__ void stsBk_bf(uint32_t bb, const F8& o, int tid) {
    int r = tid >> 2, kq = (tid & 3) * 8;
    uint32_t a = bb + 20480 + r * 80 + kq * 2;
    sts_split8(a, a + 10240, o);
}
// out B (n-major rows = k=l, 128 n): k = tid>>4 (32 rows), n0 = (tid&15)*8
__device__ __forceinline__ F8 ldgBn_bf(const BSrc& bs, int bn0, int kb, int tid) {
    int k = tid >> 4, n0 = (tid & 15) * 8;
    return ldg8(brow(bs, kb + k) + bn0 + n0);
}
__device__ __forceinline__ void stsBn_bf(uint32_t bb, const F8& o, int tid) {
    int k = tid >> 4, n0 = (tid & 15) * 8;
    uint32_t a = bb + 20480 + k * 272 + n0 * 2;
    sts_split8(a, a + 8704, o);
}

// bf16x3 GEMM core: C[128,128] = A[128xK]*B[Kx128]; 512 thr, warp 32x32,
// 2x4 m16n8k16 tiles, K=32 per barrier (2 kt), double-buffered LDG prefetch.
template <int NCHUNK, bool BNMAJOR, bool EXPA>
__device__ __forceinline__ void gemm_bf16(const float* __restrict__ A, size_t lda, int am0,
                                          BSrc bs, int bn0,
                                          uint32_t* sm, float (&acc)[2][4][4]) {
    const int tid = threadIdx.x;
    const int lane = tid & 31, wid = tid >> 5;
    const int wm0 = (wid >> 2) * 32, wn0 = (wid & 3) * 32;
    const int g = lane >> 2, t4 = lane & 3;
    const uint32_t sbase = smem_u32(sm);

#pragma unroll
    for (int i = 0; i < 2; i++)
#pragma unroll
        for (int j = 0; j < 4; j++)
#pragma unroll
            for (int q = 0; q < 4; q++) acc[i][j][q] = 0.f;

    F8 ra = ldgA_bf<EXPA>(A, lda, am0, 0, tid);
    F8 rb = BNMAJOR ? ldgBn_bf(bs, bn0, 0, tid) : ldgBk_bf(bs, bn0, 0, tid);

    // per-thread constant LDSM address parts (bytes)
    const uint32_t a_base = (wm0 + (lane & 15)) * 80 + ((lane >> 4) * 16);
    const uint32_t bt_base = (lane & 15) * 272 + (wn0 * 2) + ((lane >> 4) * 16);

#pragma unroll 1
    for (int c = 0; c < NCHUNK; c++) {
        const uint32_t bb = sbase + (c & 1) * BUF_BF;
        stsA_bf(bb, ra, tid);
        if (BNMAJOR) stsBn_bf(bb, rb, tid); else stsBk_bf(bb, rb, tid);
        __syncthreads();
        if (c + 1 < NCHUNK) {
            ra = ldgA_bf<EXPA>(A, lda, am0, (c + 1) * 32, tid);
            rb = BNMAJOR ? ldgBn_bf(bs, bn0, (c + 1) * 32, tid)
                         : ldgBk_bf(bs, bn0, (c + 1) * 32, tid);
        }
        const uint32_t* Bw = (const uint32_t*)sm + ((c & 1) * BUF_BF + 20480) / 4;

#pragma unroll
        for (int kt = 0; kt < 2; kt++) {
            uint32_t ah[2][4], al[2][4];
#pragma unroll
            for (int i = 0; i < 2; i++) {
                uint32_t ad = bb + a_base + i * 16 * 80 + kt * 32;
                ldsm4(ah[i][0], ah[i][1], ah[i][2], ah[i][3], ad);
                ldsm4(al[i][0], al[i][1], al[i][2], al[i][3], ad + 10240);
            }
            uint32_t bh[4][2], bl[4][2];
            if (BNMAJOR) {
#pragma unroll
                for (int j2 = 0; j2 < 2; j2++) {
                    uint32_t bd = bb + 20480 + bt_base + kt * 16 * 272 + j2 * 32;
                    uint32_t r0, r1, r2, r3;
                    ldsm4t(r0, r1, r2, r3, bd);
                    bh[j2 * 2][0] = r0;     bh[j2 * 2][1] = r1;
                    bh[j2 * 2 + 1][0] = r2; bh[j2 * 2 + 1][1] = r3;
                    ldsm4t(r0, r1, r2, r3, bd + 8704);
                    bl[j2 * 2][0] = r0;     bl[j2 * 2][1] = r1;
                    bl[j2 * 2 + 1][0] = r2; bl[j2 * 2 + 1][1] = r3;
                }
            } else {
#pragma unroll
                for (int j = 0; j < 4; j++) {
                    int w = (wn0 + j * 8 + g) * 20 + kt * 8 + t4;
                    bh[j][0] = Bw[w];        bh[j][1] = Bw[w + 4];
                    bl[j][0] = Bw[w + 2560]; bl[j][1] = Bw[w + 2564];
                }
            }
#pragma unroll
            for (int i = 0; i < 2; i++)
#pragma unroll
                for (int j = 0; j < 4; j++) mma16(acc[i][j], ah[i], bh[j]);
#pragma unroll
            for (int i = 0; i < 2; i++)
#pragma unroll
                for (int j = 0; j < 4; j++) mma16(acc[i][j], ah[i], bl[j]);
#pragma unroll
            for (int i = 0; i < 2; i++)
#pragma unroll
                for (int j = 0; j < 4; j++) mma16(acc[i][j], al[i], bh[j]);
        }
        __syncthreads();
    }
}

// ---------------------------------------------------------------------------
// Shared epilogue
// ---------------------------------------------------------------------------
__device__ __forceinline__ void store_acc(float (&acc)[2][4][4], float* __restrict__ dst,
                                          size_t ldd, const float* __restrict__ rowscale) {
    const int tid = threadIdx.x;
    const int lane = tid & 31, wid = tid >> 5;
    const int wm0 = (wid >> 2) * 32, wn0 = (wid & 3) * 32;
    const int g = lane >> 2, t4 = lane & 3;
#pragma unroll
    for (int i = 0; i < 2; i++) {
        int r0 = wm0 + i * 16 + g;
        float s0 = rowscale ? rowscale[r0] : 1.f;
        float s1 = rowscale ? rowscale[r0 + 8] : 1.f;
#pragma unroll
        for (int j = 0; j < 4; j++) {
            int cn = wn0 + j * 8 + t4 * 2;
            *(float2*)&dst[(size_t)r0 * ldd + cn] =
                make_float2(acc[i][j][0] * s0, acc[i][j][1] * s0);
            *(float2*)&dst[(size_t)(r0 + 8) * ldd + cn] =
                make_float2(acc[i][j][2] * s1, acc[i][j][3] * s1);
        }
    }
}

// ---------------------------------------------------------------------------
// Kernels
// ---------------------------------------------------------------------------
extern __shared__ uint32_t dsm_u32[];

// QKV (tf32x3, unchanged from best round)
__global__ __launch_bounds__(512, 1)
void k_qkv(const float* __restrict__ X, const float* __restrict__ Wq,
           const float* __restrict__ Wk, const float* __restrict__ Wv) {
    int z = blockIdx.x >> 5, head = blockIdx.x & 31, bm0 = blockIdx.y * 128;
    const float* W = (z == 0) ? Wq : (z == 1) ? Wk : Wv;
    BSrc bs{W, W, Kdim, (size_t)Nn};
    float acc[2][4][4];
    gemm_tf32<Kdim / 32>(X, Kdim, bm0, bs, head * 128, dsm_u32, acc);
    float* dst = (z == 0) ? g_q  + ((size_t)head * Mm + bm0) * Dd
               : (z == 1) ? g_Kn + ((size_t)head * Mm + bm0) * Dd
                          : g_Vn + ((size_t)head * Mm + bm0) * Dd;
    store_acc(acc, dst, Dd, nullptr);
}

// Scores (bf16x3): S = q @ K^T; B = K-cache rows (K-major), scalar packed frags
__global__ __launch_bounds__(512, 1)
void k_scores(const float* __restrict__ cacheK) {
    int h = blockIdx.z, bm0 = blockIdx.y * 128, l0 = blockIdx.x * 128;
    BSrc bs{cacheK + (size_t)h * Ll * Dd, g_Kn + (size_t)h * Mm * Dd, Pp, (size_t)Dd};
    float acc[2][4][4];
    gemm_bf16<Dd / 32, false, false>(g_q + (size_t)h * Mm * Dd, Dd, bm0, bs, l0,
                                     dsm_u32, acc);
    store_acc(acc, g_S + ((size_t)h * Mm + bm0) * Ll + l0, Ll, nullptr);
}

// Output (bf16x3): out = (exp(S) @ V) * inv; V n-major via ldmatrix.trans
__global__ __launch_bounds__(512, 1)
void k_out(const float* __restrict__ cacheV, float* __restrict__ dout) {
    int h = blockIdx.y, bm0 = blockIdx.x * 128;
    BSrc bs{cacheV + (size_t)h * Ll * Dd, g_Vn + (size_t)h * Mm * Dd, Pp, (size_t)Dd};
    float acc[2][4][4];
    gemm_bf16<Ll / 32, true, true>(g_S + (size_t)h * Mm * Ll, Ll, bm0, bs, 0,
                                   dsm_u32, acc);
    store_acc(acc, dout + (size_t)bm0 * Nn + h * Dd, Nn, g_invs + h * Mm + bm0);
}

// Dual-exp row kernel: reads raw S, writes normalized perturb + invs.
__global__ __launch_bounds__(256)
void softmax_rows(const float* __restrict__ noise, float* __restrict__ dout) {
    const int row = blockIdx.x;  // h*Mm + m
    const float* S = g_S + (size_t)row * Ll;
    const float* nz = noise + (size_t)row * Ll;
    float* pout = dout + OUT0 + (size_t)row * Ll;
    __shared__ float ep[Ll];
    __shared__ float r1[256], r2[256];
    const int tid = threadIdx.x;

    float ss = 0.f, sp = 0.f;
    for (int l = tid; l < Ll; l += 256) {
        float s = S[l];
        ss += __expf(s);
        float e2 = __expf((s + nz[l]) * (1.0f / 1.5f));
        ep[l] = e2;
        sp += e2;
    }
    r1[tid] = ss; r2[tid] = sp;
    __syncthreads();
    for (int st = 128; st > 0; st >>= 1) {
        if (tid < st) { r1[tid] += r1[tid + st]; r2[tid] += r2[tid + st]; }
        __syncthreads();
    }
    if (tid == 0) g_invs[row] = 1.0f / r1[0];
    const float ip = 1.0f / r2[0];
    for (int l = tid; l < Ll; l += 256) pout[l] = ep[l] * ip;
}

// ---------------------------------------------------------------------------
// Launch
// ---------------------------------------------------------------------------
extern "C" void kernel_launch(void* const* d_in, const int* in_sizes, int n_in,
                              void* d_out, int out_size) {
    const float* X      = (const float*)d_in[0];
    const float* Wq     = (const float*)d_in[1];
    const float* Wk     = (const float*)d_in[2];
    const float* Wv     = (const float*)d_in[3];
    const float* noise  = (const float*)d_in[4];
    const float* cacheK = (const float*)d_in[5];
    const float* cacheV = (const float*)d_in[6];
    float* out = (float*)d_out;
    (void)in_sizes; (void)n_in; (void)out_size;   // P is static (3584)

    cudaFuncSetAttribute(k_qkv,    cudaFuncAttributeMaxDynamicSharedMemorySize, SMEMSZ_TF);
    cudaFuncSetAttribute(k_scores, cudaFuncAttributeMaxDynamicSharedMemorySize, SMEMSZ_BF);
    cudaFuncSetAttribute(k_out,    cudaFuncAttributeMaxDynamicSharedMemorySize, SMEMSZ_BF);

    k_qkv<<<dim3(96, 4), 512, SMEMSZ_TF>>>(X, Wq, Wk, Wv);
    k_scores<<<dim3(32, 4, 32), 512, SMEMSZ_BF>>>(cacheK);
    softmax_rows<<<Hh * Mm, 256>>>(noise, out);
    k_out<<<dim3(4, 32), 512, SMEMSZ_BF>>>(cacheV, out);
}

// round 17
// speedup vs baseline: 1.1886x; 1.0260x over previous
#include <cuda_runtime.h>
#include <cstdint>
#include <cstddef>

// Problem constants (static in reference)
constexpr int Mm = 512, Nn = 4096, Kdim = 4096, Dd = 128, Hh = 32, Ll = 4096, Pp = 3584;
constexpr size_t OUT0 = (size_t)Mm * Nn;

// Scratch (device globals: allocation-free per harness rules)
__device__ float g_q [(size_t)Hh * Mm * Dd];   // 8 MB [H][M][D]
__device__ float g_Kn[(size_t)Hh * Mm * Dd];   // 8 MB new K rows [H][M][D]
__device__ float g_Vn[(size_t)Hh * Mm * Dd];   // 8 MB new V rows [H][M][D]
__device__ float g_S [(size_t)Hh * Mm * Ll];   // 256 MB raw scores [H*M][L]

// ---------------------------------------------------------------------------
// PTX helpers (all baseline, no sm_103a-suffixed features)
// ---------------------------------------------------------------------------
__device__ __forceinline__ uint32_t smem_u32(const void* p) {
    uint32_t a;
    asm("{ .reg .u64 t; cvta.to.shared.u64 t, %1; cvt.u32.u64 %0, t; }" : "=r"(a) : "l"(p));
    return a;
}
// tf32 mask split (for qkv)
__device__ __forceinline__ void tf32split(uint32_t fraw, uint32_t& hi, uint32_t& lo) {
    hi = fraw & 0xFFFFE000u;
    lo = __float_as_uint(__uint_as_float(fraw) - __uint_as_float(hi));
}
// bf16 pair split: (f0,f1) -> packed hi bf16x2 (f0 in low half) + packed lo bf16x2
__device__ __forceinline__ void bf16split2(float f0, float f1, uint32_t& h, uint32_t& l) {
    asm("cvt.rn.bf16x2.f32 %0, %1, %2;" : "=r"(h) : "f"(f1), "f"(f0));
    float h0 = __uint_as_float(h << 16);
    float h1 = __uint_as_float(h & 0xFFFF0000u);
    float r0 = f0 - h0, r1 = f1 - h1;
    asm("cvt.rn.bf16x2.f32 %0, %1, %2;" : "=r"(l) : "f"(r1), "f"(r0));
}
__device__ __forceinline__ void mma8(float* c, const uint32_t* a, const uint32_t* b) {
    asm("mma.sync.aligned.m16n8k8.row.col.f32.tf32.tf32.f32 "
        "{%0,%1,%2,%3}, {%4,%5,%6,%7}, {%8,%9}, {%0,%1,%2,%3};"
        : "+f"(c[0]), "+f"(c[1]), "+f"(c[2]), "+f"(c[3])
        : "r"(a[0]), "r"(a[1]), "r"(a[2]), "r"(a[3]), "r"(b[0]), "r"(b[1]));
}
__device__ __forceinline__ void mma16(float* c, const uint32_t* a, const uint32_t* b) {
    asm("mma.sync.aligned.m16n8k16.row.col.f32.bf16.bf16.f32 "
        "{%0,%1,%2,%3}, {%4,%5,%6,%7}, {%8,%9}, {%0,%1,%2,%3};"
        : "+f"(c[0]), "+f"(c[1]), "+f"(c[2]), "+f"(c[3])
        : "r"(a[0]), "r"(a[1]), "r"(a[2]), "r"(a[3]), "r"(b[0]), "r"(b[1]));
}
__device__ __forceinline__ void ldsm4(uint32_t& r0, uint32_t& r1, uint32_t& r2, uint32_t& r3,
                                      uint32_t addr) {
    asm volatile("ldmatrix.sync.aligned.m8n8.x4.shared.b16 {%0,%1,%2,%3}, [%4];"
                 : "=r"(r0), "=r"(r1), "=r"(r2), "=r"(r3) : "r"(addr));
}
__device__ __forceinline__ void ldsm4t(uint32_t& r0, uint32_t& r1, uint32_t& r2, uint32_t& r3,
                                       uint32_t addr) {
    asm volatile("ldmatrix.sync.aligned.m8n8.x4.trans.shared.b16 {%0,%1,%2,%3}, [%4];"
                 : "=r"(r0), "=r"(r1), "=r"(r2), "=r"(r3) : "r"(addr));
}
__device__ __forceinline__ void cpasync16(uint32_t dst, const float* src) {
    asm volatile("cp.async.cg.shared.global [%0], [%1], 16;" :: "r"(dst), "l"(src));
}
#define CP_COMMIT() asm volatile("cp.async.commit_group;" ::: "memory")
#define CP_WAIT2()  asm volatile("cp.async.wait_group 2;" ::: "memory")
#define STS128(a, x, y, z, w) \
    asm volatile("st.shared.v4.b32 [%0], {%1,%2,%3,%4};" \
                 :: "r"(a), "r"(x), "r"(y), "r"(z), "r"(w) : "memory")

// B rows from two sources split at `split` (cache vs freshly-projected rows)
struct BSrc { const float* p0; const float* p1; int split; size_t ld; };
__device__ __forceinline__ const float* brow(const BSrc& s, int r) {
    return (r < s.split) ? s.p0 + (size_t)r * s.ld : s.p1 + (size_t)(r - s.split) * s.ld;
}

// ===========================================================================
// Part 1: tf32 GEMM for QKV
// ===========================================================================
#define A_STR 36
#define B_STR 140
#define B_OFF_W 4608
#define STAGE_W 9216
constexpr int SMEMSZ_TF = 4 * STAGE_W * 4;   // 147456 B

__device__ __forceinline__ void issueA(uint32_t sb, const float* __restrict__ A,
                                       size_t lda, int am0, int kb, int tid) {
    int r = tid >> 2, kq = (tid & 3) * 8;
    const float* src = A + (size_t)(am0 + r) * lda + kb + kq;
    uint32_t dst = sb + (r * A_STR + kq) * 4;
    cpasync16(dst, src);
    cpasync16(dst + 16, src + 4);
}
__device__ __forceinline__ void issueB(uint32_t sb, const BSrc& bs, int bn0, int kb, int tid) {
    int k = tid >> 4, n0 = (tid & 15) * 8;
    const float* src = brow(bs, kb + k) + bn0 + n0;
    uint32_t dst = sb + B_OFF_W * 4 + (k * B_STR + n0) * 4;
    cpasync16(dst, src);
    cpasync16(dst + 16, src + 4);
}

template <int NCHUNK>
__device__ __forceinline__ void gemm_tf32(const float* __restrict__ A, size_t lda, int am0,
                                          BSrc bs, int bn0,
                                          uint32_t* sm, float (&acc)[2][4][4]) {
    const int tid = threadIdx.x;
    const int lane = tid & 31, wid = tid >> 5;
    const int wm0 = (wid >> 2) * 32, wn0 = (wid & 3) * 32;
    const int g = lane >> 2, t4 = lane & 3;
    const uint32_t sbase = smem_u32(sm);

#pragma unroll
    for (int i = 0; i < 2; i++)
#pragma unroll
        for (int j = 0; j < 4; j++)
#pragma unroll
            for (int q = 0; q < 4; q++) acc[i][j][q] = 0.f;

    issueA(sbase, A, lda, am0, 0, tid);
    issueB(sbase, bs, bn0, 0, tid);
    CP_COMMIT();
    issueA(sbase + STAGE_W * 4, A, lda, am0, 32, tid);
    issueB(sbase + STAGE_W * 4, bs, bn0, 32, tid);
    CP_COMMIT();
    issueA(sbase + 2 * STAGE_W * 4, A, lda, am0, 64, tid);
    issueB(sbase + 2 * STAGE_W * 4, bs, bn0, 64, tid);
    CP_COMMIT();

    const uint32_t a_rowbase = (wm0 + (lane & 15)) * A_STR + ((lane >> 4) << 2);

#pragma unroll 1
    for (int c = 0; c < NCHUNK; c++) {
        // Single barrier per chunk: every thread reaches here only after its
        // chunk c-1 MMAs, so the ring slot written below (c+3 == c-1 mod 4)
        // is already drained by all warps.
        CP_WAIT2();
        __syncthreads();
        if (c + 3 < NCHUNK) {
            uint32_t nb = sbase + ((c + 3) & 3) * STAGE_W * 4;
            issueA(nb, A, lda, am0, (c + 3) * 32, tid);
            issueB(nb, bs, bn0, (c + 3) * 32, tid);
        }
        CP_COMMIT();

        const uint32_t aB = sbase + (c & 3) * STAGE_W * 4;
        const uint32_t* Bs = (const uint32_t*)sm + (c & 3) * STAGE_W + B_OFF_W;

#pragma unroll
        for (int kt = 0; kt < 4; kt++) {
            uint32_t araw[2][4], ah[2][4], al[2][4];
#pragma unroll
            for (int i = 0; i < 2; i++)
                ldsm4(araw[i][0], araw[i][1], araw[i][2], araw[i][3],
                      aB + (a_rowbase + i * 16 * A_STR + kt * 8) * 4);
#pragma unroll
            for (int i = 0; i < 2; i++)
#pragma unroll
                for (int q = 0; q < 4; q++) tf32split(araw[i][q], ah[i][q], al[i][q]);
            uint32_t bh[4][2], bl[4][2];
            const int kc = kt * 8 + t4;
#pragma unroll
            for (int j = 0; j < 4; j++) {
                tf32split(Bs[kc * B_STR + wn0 + j * 8 + g], bh[j][0], bl[j][0]);
                tf32split(Bs[(kc + 4) * B_STR + wn0 + j * 8 + g], bh[j][1], bl[j][1]);
            }
#pragma unroll
            for (int i = 0; i < 2; i++)
#pragma unroll
                for (int j = 0; j < 4; j++) mma8(acc[i][j], ah[i], bh[j]);
#pragma unroll
            for (int i = 0; i < 2; i++)
#pragma unroll
                for (int j = 0; j < 4; j++) mma8(acc[i][j], ah[i], bl[j]);
#pragma unroll
            for (int i = 0; i < 2; i++)
#pragma unroll
                for (int j = 0; j < 4; j++) mma8(acc[i][j], al[i], bh[j]);
        }
    }
}

// ===========================================================================
// Part 2: bf16x3 GEMM for scores & out (m16n8k16, hi/lo split at stage time)
// SMEM per buffer (bytes):
//   Ahi [128 rows x 80B] @0, Alo @10240          (K-major packed bf16 pairs)
//   scores B (K-major packed, 128 rows x 80B): Bhi @20480, Blo @30720
//   out   B (n-major bf16 [32 k x 272B]):       Bhi @20480, Blo @29184
// Buffer stride 40960 B, double-buffered (81920 total).
// ===========================================================================
constexpr int BUF_BF = 40960;
constexpr int SMEMSZ_BF = 2 * BUF_BF;

struct F8 { float v[8]; };
__device__ __forceinline__ F8 ldg8(const float* p) {
    F8 o;
    float4 a = *(const float4*)p, b = *(const float4*)(p + 4);
    o.v[0] = a.x; o.v[1] = a.y; o.v[2] = a.z; o.v[3] = a.w;
    o.v[4] = b.x; o.v[5] = b.y; o.v[6] = b.z; o.v[7] = b.w;
    return o;
}
__device__ __forceinline__ void sts_split8(uint32_t hiaddr, uint32_t loaddr, const F8& o) {
    uint32_t h[4], l[4];
#pragma unroll
    for (int i = 0; i < 4; i++) bf16split2(o.v[2 * i], o.v[2 * i + 1], h[i], l[i]);
    STS128(hiaddr, h[0], h[1], h[2], h[3]);
    STS128(loaddr, l[0], l[1], l[2], l[3]);
}

template <bool EXPA>
__device__ __forceinline__ F8 ldgA_bf(const float* __restrict__ A, size_t lda,
                                      int am0, int kb, int tid) {
    int r = tid >> 2, kq = (tid & 3) * 8;
    F8 o = ldg8(A + (size_t)(am0 + r) * lda + kb + kq);
    if (EXPA) {
#pragma unroll
        for (int i = 0; i < 8; i++) o.v[i] = __expf(o.v[i]);
    }
    return o;
}
__device__ __forceinline__ void stsA_bf(uint32_t bb, const F8& o, int tid) {
    int r = tid >> 2, kq = (tid & 3) * 8;
    uint32_t a = bb + r * 80 + kq * 2;
    sts_split8(a, a + 10240, o);
}
__device__ __forceinline__ F8 ldgBk_bf(const BSrc& bs, int bn0, int kb, int tid) {
    int r = tid >> 2, kq = (tid & 3) * 8;
    return ldg8(brow(bs, bn0 + r) + kb + kq);
}
__device__ __forceinline__ void stsBk_bf(uint32_t bb, const F8& o, int tid) {
    int r = tid >> 2, kq = (tid & 3) * 8;
    uint32_t a = bb + 20480 + r * 80 + kq * 2;
    sts_split8(a, a + 10240, o);
}
__device__ __forceinline__ F8 ldgBn_bf(const BSrc& bs, int bn0, int kb, int tid) {
    int k = tid >> 4, n0 = (tid & 15) * 8;
    return ldg8(brow(bs, kb + k) + bn0 + n0);
}
__device__ __forceinline__ void stsBn_bf(uint32_t bb, const F8& o, int tid) {
    int k = tid >> 4, n0 = (tid & 15) * 8;
    uint32_t a = bb + 20480 + k * 272 + n0 * 2;
    sts_split8(a, a + 8704, o);
}

// bf16x3 GEMM core. When EXPA, exp'd A-values are accumulated into asum:
// thread tid stages row r = tid>>2 with disjoint k-slices across chunks, so
// asum over the mainloop is a per-(thread,row) partial of sum_l exp(s).
template <int NCHUNK, bool BNMAJOR, bool EXPA>
__device__ __forceinline__ void gemm_bf16(const float* __restrict__ A, size_t lda, int am0,
                                          BSrc bs, int bn0,
                                          uint32_t* sm, float (&acc)[2][4][4],
                                          float& asum) {
    const int tid = threadIdx.x;
    const int lane = tid & 31, wid = tid >> 5;
    const int wm0 = (wid >> 2) * 32, wn0 = (wid & 3) * 32;
    const int g = lane >> 2, t4 = lane & 3;
    const uint32_t sbase = smem_u32(sm);

#pragma unroll
    for (int i = 0; i < 2; i++)
#pragma unroll
        for (int j = 0; j < 4; j++)
#pragma unroll
            for (int q = 0; q < 4; q++) acc[i][j][q] = 0.f;

    F8 ra = ldgA_bf<EXPA>(A, lda, am0, 0, tid);
    if (EXPA) {
#pragma unroll
        for (int i = 0; i < 8; i++) asum += ra.v[i];
    }
    F8 rb = BNMAJOR ? ldgBn_bf(bs, bn0, 0, tid) : ldgBk_bf(bs, bn0, 0, tid);

    const uint32_t a_base = (wm0 + (lane & 15)) * 80 + ((lane >> 4) * 16);
    const uint32_t bt_base = (lane & 15) * 272 + (wn0 * 2) + ((lane >> 4) * 16);

#pragma unroll 1
    for (int c = 0; c < NCHUNK; c++) {
        const uint32_t bb = sbase + (c & 1) * BUF_BF;
        stsA_bf(bb, ra, tid);
        if (BNMAJOR) stsBn_bf(bb, rb, tid); else stsBk_bf(bb, rb, tid);
        // Single barrier per chunk: STS above targets the buffer last read in
        // chunk c-2; every thread passed the barrier of chunk c-1 only after
        // finishing its chunk c-2 MMAs, so the slot is drained.
        __syncthreads();
        if (c + 1 < NCHUNK) {
            ra = ldgA_bf<EXPA>(A, lda, am0, (c + 1) * 32, tid);
            if (EXPA) {
#pragma unroll
                for (int i = 0; i < 8; i++) asum += ra.v[i];
            }
            rb = BNMAJOR ? ldgBn_bf(bs, bn0, (c + 1) * 32, tid)
                         : ldgBk_bf(bs, bn0, (c + 1) * 32, tid);
        }
        const uint32_t* Bw = (const uint32_t*)sm + ((c & 1) * BUF_BF + 20480) / 4;

#pragma unroll
        for (int kt = 0; kt < 2; kt++) {
            uint32_t ah[2][4], al[2][4];
#pragma unroll
            for (int i = 0; i < 2; i++) {
                uint32_t ad = bb + a_base + i * 16 * 80 + kt * 32;
                ldsm4(ah[i][0], ah[i][1], ah[i][2], ah[i][3], ad);
                ldsm4(al[i][0], al[i][1], al[i][2], al[i][3], ad + 10240);
            }
            uint32_t bh[4][2], bl[4][2];
            if (BNMAJOR) {
#pragma unroll
                for (int j2 = 0; j2 < 2; j2++) {
                    uint32_t bd = bb + 20480 + bt_base + kt * 16 * 272 + j2 * 32;
                    uint32_t r0, r1, r2, r3;
                    ldsm4t(r0, r1, r2, r3, bd);
                    bh[j2 * 2][0] = r0;     bh[j2 * 2][1] = r1;
                    bh[j2 * 2 + 1][0] = r2; bh[j2 * 2 + 1][1] = r3;
                    ldsm4t(r0, r1, r2, r3, bd + 8704);
                    bl[j2 * 2][0] = r0;     bl[j2 * 2][1] = r1;
                    bl[j2 * 2 + 1][0] = r2; bl[j2 * 2 + 1][1] = r3;
                }
            } else {
#pragma unroll
                for (int j = 0; j < 4; j++) {
                    int w = (wn0 + j * 8 + g) * 20 + kt * 8 + t4;
                    bh[j][0] = Bw[w];        bh[j][1] = Bw[w + 4];
                    bl[j][0] = Bw[w + 2560]; bl[j][1] = Bw[w + 2564];
                }
            }
#pragma unroll
            for (int i = 0; i < 2; i++)
#pragma unroll
                for (int j = 0; j < 4; j++) mma16(acc[i][j], ah[i], bh[j]);
#pragma unroll
            for (int i = 0; i < 2; i++)
#pragma unroll
                for (int j = 0; j < 4; j++) mma16(acc[i][j], ah[i], bl[j]);
#pragma unroll
            for (int i = 0; i < 2; i++)
#pragma unroll
                for (int j = 0; j < 4; j++) mma16(acc[i][j], al[i], bh[j]);
        }
    }
    __syncthreads();   // drain last chunk's smem reads before epilogue reuse
}

// ---------------------------------------------------------------------------
// Shared epilogue
// ---------------------------------------------------------------------------
__device__ __forceinline__ void store_acc(float (&acc)[2][4][4], float* __restrict__ dst,
                                          size_t ldd, const float* __restrict__ rowscale) {
    const int tid = threadIdx.x;
    const int lane = tid & 31, wid = tid >> 5;
    const int wm0 = (wid >> 2) * 32, wn0 = (wid & 3) * 32;
    const int g = lane >> 2, t4 = lane & 3;
#pragma unroll
    for (int i = 0; i < 2; i++) {
        int r0 = wm0 + i * 16 + g;
        float s0 = rowscale ? rowscale[r0] : 1.f;
        float s1 = rowscale ? rowscale[r0 + 8] : 1.f;
#pragma unroll
        for (int j = 0; j < 4; j++) {
            int cn = wn0 + j * 8 + t4 * 2;
            *(float2*)&dst[(size_t)r0 * ldd + cn] =
                make_float2(acc[i][j][0] * s0, acc[i][j][1] * s0);
            *(float2*)&dst[(size_t)(r0 + 8) * ldd + cn] =
                make_float2(acc[i][j][2] * s1, acc[i][j][3] * s1);
        }
    }
}

// ---------------------------------------------------------------------------
// Kernels
// ---------------------------------------------------------------------------
extern __shared__ uint32_t dsm_u32[];

// QKV (tf32x3)
__global__ __launch_bounds__(512, 1)
void k_qkv(const float* __restrict__ X, const float* __restrict__ Wq,
           const float* __restrict__ Wk, const float* __restrict__ Wv) {
    int z = blockIdx.x >> 5, head = blockIdx.x & 31, bm0 = blockIdx.y * 128;
    const float* W = (z == 0) ? Wq : (z == 1) ? Wk : Wv;
    BSrc bs{W, W, Kdim, (size_t)Nn};
    float acc[2][4][4];
    gemm_tf32<Kdim / 32>(X, Kdim, bm0, bs, head * 128, dsm_u32, acc);
    float* dst = (z == 0) ? g_q  + ((size_t)head * Mm + bm0) * Dd
               : (z == 1) ? g_Kn + ((size_t)head * Mm + bm0) * Dd
                          : g_Vn + ((size_t)head * Mm + bm0) * Dd;
    store_acc(acc, dst, Dd, nullptr);
}

// Scores (bf16x3): S = q @ K^T
__global__ __launch_bounds__(512, 1)
void k_scores(const float* __restrict__ cacheK) {
    int h = blockIdx.z, bm0 = blockIdx.y * 128, l0 = blockIdx.x * 128;
    BSrc bs{cacheK + (size_t)h * Ll * Dd, g_Kn + (size_t)h * Mm * Dd, Pp, (size_t)Dd};
    float acc[2][4][4];
    float dummy = 0.f;
    gemm_bf16<Dd / 32, false, false>(g_q + (size_t)h * Mm * Dd, Dd, bm0, bs, l0,
                                     dsm_u32, acc, dummy);
    store_acc(acc, g_S + ((size_t)h * Mm + bm0) * Ll + l0, Ll, nullptr);
}

// Output (bf16x3): out = (exp(S) @ V) / rowsum, rowsum computed in-kernel from
// the exact fp32 exp values at stage time (thread tid owns row tid>>2).
__global__ __launch_bounds__(512, 1)
void k_out(const float* __restrict__ cacheV, float* __restrict__ dout) {
    int h = blockIdx.y, bm0 = blockIdx.x * 128;
    BSrc bs{cacheV + (size_t)h * Ll * Dd, g_Vn + (size_t)h * Mm * Dd, Pp, (size_t)Dd};
    float acc[2][4][4];
    float lsum = 0.f;
    gemm_bf16<Ll / 32, true, true>(g_S + (size_t)h * Mm * Ll, Ll, bm0, bs, 0,
                                   dsm_u32, acc, lsum);
    // 4 threads per row (tid>>2): reduce and invert into smem
    lsum += __shfl_xor_sync(0xFFFFFFFFu, lsum, 1);
    lsum += __shfl_xor_sync(0xFFFFFFFFu, lsum, 2);
    float* rowinv = (float*)dsm_u32;
    int tid = threadIdx.x;
    if ((tid & 3) == 0) rowinv[tid >> 2] = 1.0f / lsum;
    __syncthreads();
    store_acc(acc, dout + (size_t)bm0 * Nn + h * Dd, Nn, rowinv);
}

// Perturb-only row kernel: one exp per element (clean-sum moved into k_out).
__global__ __launch_bounds__(256)
void softmax_rows(const float* __restrict__ noise, float* __restrict__ dout) {
    const int row = blockIdx.x;  // h*Mm + m
    const float* S = g_S + (size_t)row * Ll;
    const float* nz = noise + (size_t)row * Ll;
    float* pout = dout + OUT0 + (size_t)row * Ll;
    __shared__ float ep[Ll];
    __shared__ float r2[256];
    const int tid = threadIdx.x;

    float sp = 0.f;
    for (int l = tid; l < Ll; l += 256) {
        float e2 = __expf((S[l] + nz[l]) * (1.0f / 1.5f));
        ep[l] = e2;
        sp += e2;
    }
    r2[tid] = sp;
    __syncthreads();
    for (int st = 128; st > 0; st >>= 1) {
        if (tid < st) r2[tid] += r2[tid + st];
        __syncthreads();
    }
    const float ip = 1.0f / r2[0];
    for (int l = tid; l < Ll; l += 256) pout[l] = ep[l] * ip;
}

// ---------------------------------------------------------------------------
// Launch
// ---------------------------------------------------------------------------
extern "C" void kernel_launch(void* const* d_in, const int* in_sizes, int n_in,
                              void* d_out, int out_size) {
    const float* X      = (const float*)d_in[0];
    const float* Wq     = (const float*)d_in[1];
    const float* Wk     = (const float*)d_in[2];
    const float* Wv     = (const float*)d_in[3];
    const float* noise  = (const float*)d_in[4];
    const float* cacheK = (const float*)d_in[5];
    const float* cacheV = (const float*)d_in[6];
    float* out = (float*)d_out;
    (void)in_sizes; (void)n_in; (void)out_size;   // P is static (3584)

    cudaFuncSetAttribute(k_qkv,    cudaFuncAttributeMaxDynamicSharedMemorySize, SMEMSZ_TF);
    cudaFuncSetAttribute(k_scores, cudaFuncAttributeMaxDynamicSharedMemorySize, SMEMSZ_BF);
    cudaFuncSetAttribute(k_out,    cudaFuncAttributeMaxDynamicSharedMemorySize, SMEMSZ_BF);

    k_qkv<<<dim3(96, 4), 512, SMEMSZ_TF>>>(X, Wq, Wk, Wv);
    k_scores<<<dim3(32, 4, 32), 512, SMEMSZ_BF>>>(cacheK);
    k_out<<<dim3(4, 32), 512, SMEMSZ_BF>>>(cacheV, out);
    softmax_rows<<<Hh * Mm, 256>>>(noise, out);
}